// round 13
// baseline (speedup 1.0000x reference)
#include <cuda_runtime.h>
#include <math.h>

#define B_   16
#define T_   128
#define I_   256
#define H_   256
#define NZ_  1024          // 4*H
#define NBLK 128           // 4 groups x 32 blocks
#define GRPB 32            // blocks per group
#define ARRV (GRPB * 8)    // arrivals per step: one per WARP

typedef unsigned long long ull;

// Scratch (static device globals: no allocation)
__device__ float    g_xz[T_ * NZ_ * B_];   // [t][n][b]  8 MB
__device__ float    g_h[2][B_ * H_];       // ping-pong hidden state [b][u]
__device__ unsigned g_arr[4 * T_ * 32];    // per-(group,step) counters, 128B apart

// fast transcendentals: ex2.approx + rcp.approx (~1e-6 rel err each)
__device__ __forceinline__ float fsigmoid(float x) {
    float e; asm("ex2.approx.ftz.f32 %0, %1;" : "=f"(e) : "f"(-1.4426950408889634f * x));
    float r; asm("rcp.approx.ftz.f32 %0, %1;" : "=f"(r) : "f"(1.0f + e));
    return r;
}
__device__ __forceinline__ float ftanh_(float x) {
    x = fminf(fmaxf(x, -30.0f), 30.0f);
    float e; asm("ex2.approx.ftz.f32 %0, %1;" : "=f"(e) : "f"(2.8853900817779268f * x));
    float r; asm("rcp.approx.ftz.f32 %0, %1;" : "=f"(r) : "f"(e + 1.0f));
    return (e - 1.0f) * r;
}

// packed f32x2 helpers (sm_100+)
__device__ __forceinline__ ull pack2(float lo, float hi) {
    ull r; asm("mov.b64 %0, {%1,%2};" : "=l"(r) : "f"(lo), "f"(hi)); return r;
}
__device__ __forceinline__ void unpack2(ull v, float& lo, float& hi) {
    asm("mov.b64 {%0,%1}, %2;" : "=f"(lo), "=f"(hi) : "l"(v));
}
__device__ __forceinline__ ull fma2(ull a, ull b, ull c) {
    ull d; asm("fma.rn.f32x2 %0, %1, %2, %3;" : "=l"(d) : "l"(a), "l"(b), "l"(c));
    return d;
}

// ---------------------------------------------------------------------------
// Kernel 1: XZ[t][n][b] = sum_k x[b][t][k] * Wih[k][n]   (k < 256 rows of Wih)
// grid (8 n-blocks of 128 cols, 128 t), 128 threads
// Also resets the group counters (graph-replay safe: runs before kernel 2).
// ---------------------------------------------------------------------------
__global__ void __launch_bounds__(128)
xz_kernel(const float* __restrict__ x, const float* __restrict__ Wih)
{
    if (blockIdx.y == 0) {
        int base = (blockIdx.x * 128 + threadIdx.x) * 16;  // 1024 thr x 16 = 16384
        #pragma unroll
        for (int i = 0; i < 16; i++) g_arr[base + i] = 0u;
    }

    __shared__ float x_s[I_ * B_];     // [k][b], 16 KB
    __shared__ float w_s[16 * 128];

    const int t   = blockIdx.y;
    const int n0  = blockIdx.x * 128;
    const int tid = threadIdx.x;

    for (int idx = tid; idx < B_ * I_; idx += 128) {
        int b = idx >> 8;
        int k = idx & 255;
        x_s[k * B_ + b] = x[(b * T_ + t) * I_ + k];
    }

    const int bq = tid >> 5;
    const int ng = tid & 31;
    const int b0 = bq * 4;
    const int nn = ng * 4;

    float acc[4][4];
    #pragma unroll
    for (int i = 0; i < 4; i++)
        #pragma unroll
        for (int j = 0; j < 4; j++) acc[i][j] = 0.f;

    for (int kb = 0; kb < 16; kb++) {
        __syncthreads();
        for (int q = tid; q < 512; q += 128) {
            int r  = q >> 5;
            int c4 = q & 31;
            ((float4*)w_s)[q] =
                ((const float4*)(Wih + (size_t)(kb * 16 + r) * NZ_ + n0))[c4];
        }
        __syncthreads();
        #pragma unroll
        for (int kk = 0; kk < 16; kk++) {
            float4 xv = *(const float4*)&x_s[(kb * 16 + kk) * B_ + b0];
            float4 wv = *(const float4*)&w_s[kk * 128 + nn];
            float xr[4] = {xv.x, xv.y, xv.z, xv.w};
            float wr_[4] = {wv.x, wv.y, wv.z, wv.w};
            #pragma unroll
            for (int i = 0; i < 4; i++)
                #pragma unroll
                for (int j = 0; j < 4; j++)
                    acc[i][j] += xr[i] * wr_[j];
        }
    }

    #pragma unroll
    for (int j = 0; j < 4; j++) {
        float4 o = make_float4(acc[0][j], acc[1][j], acc[2][j], acc[3][j]);
        *(float4*)&g_xz[(size_t)(t * NZ_ + n0 + nn + j) * B_ + b0] = o;
    }
}

// ---------------------------------------------------------------------------
// Kernel 2: persistent recurrence, 4 independent groups of 32 blocks
// (group g owns batches 4g..4g+3; block r owns units 8r..8r+7, warp = unit).
// Critical-path gemm uses the COMBINED matrix Wc = Whh + Wa (one matrix,
// half the MACs):   z_t = xz_t + A'_{t-1} + h_{t-1}@Wc
// The A' update (h_{t-1}@Wa) is a SHADOW gemm issued after publish+release,
// hidden under the next step's global wait. A'_{-1} = (out0 - h_init)@Wa.
// ---------------------------------------------------------------------------
__global__ void __launch_bounds__(256)
rec_kernel(const float* __restrict__ h_init, const float* __restrict__ c_init,
           const float* __restrict__ out0,
           const float* __restrict__ Wih,  const float* __restrict__ Whh,
           const float* __restrict__ b_ih, const float* __restrict__ b_hh,
           float* __restrict__ dout)
{
    __shared__ float h_s[4 * H_];           // 4 KB: the group's 4 batches

    const int tid   = threadIdx.x;
    const int bid   = blockIdx.x;
    const int g     = bid >> 5;    // group 0..3 -> batches 4g..4g+3
    const int r     = bid & 31;    // unit block -> units 8r..8r+7
    const int u0    = r * 8;
    const int b0    = g * 4;
    const int w     = tid >> 5;    // warp = local unit
    const int lane  = tid & 31;
    const int kc    = lane & 15;
    const int khalf = (lane >> 4) * 128;    // lanes<16: K[0:128), else K[128:256)
    const int u     = u0 + w;      // this warp's unit

    // packed weights: 32-lane split-K, k0 = khalf + 32j + 2kc, j=0..3
    // wr2c = Whh + Wa (critical path), wr2a = Wa (shadow)
    ull wr2c[4][4], wr2a[4][4];
    #pragma unroll
    for (int c = 0; c < 4; c++) {
        const int n = u + 256 * c;
        #pragma unroll
        for (int j = 0; j < 4; j++) {
            const int k0 = khalf + 32 * j + 2 * kc;
            float a0 = Wih[(size_t)(256 + k0) * NZ_ + n];
            float a1 = Wih[(size_t)(256 + k0 + 1) * NZ_ + n];
            float h0 = Whh[(size_t)k0 * NZ_ + n];
            float h1 = Whh[(size_t)(k0 + 1) * NZ_ + n];
            wr2a[c][j] = pack2(a0, a1);
            wr2c[c][j] = pack2(h0 + a0, h1 + a1);
        }
    }

    // lane-resident cell state (lanes 0..3 = batches b0..b0+3)
    float A_r[4], bias_r[4], c_r = 0.f, att_r = 0.f;
    const int bme = b0 + lane;     // this lane's batch (valid when lane<4)
    if (lane < 4) {
        #pragma unroll
        for (int c = 0; c < 4; c++)
            bias_r[c] = b_ih[u + 256 * c] + b_hh[u + 256 * c];
        c_r   = c_init[bme * H_ + u];
        att_r = out0[bme * H_ + u];          // atten includes buf[0] = out0
    }

    // single-matrix gemm + full 32-lane butterfly; every lane gets [4b][4g]
    auto do_gemm = [&](const ull (&wv)[4][4], float (&out)[4][4]) {
        ull acc2[4][4];
        #pragma unroll
        for (int i = 0; i < 4; i++)
            #pragma unroll
            for (int c = 0; c < 4; c++) acc2[i][c] = pack2(0.f, 0.f);
        #pragma unroll
        for (int j = 0; j < 4; j++) {
            const int k0 = khalf + 32 * j + 2 * kc;
            ull h0 = *(const ull*)&h_s[0 * H_ + k0];
            ull h1 = *(const ull*)&h_s[1 * H_ + k0];
            ull h2 = *(const ull*)&h_s[2 * H_ + k0];
            ull h3 = *(const ull*)&h_s[3 * H_ + k0];
            #pragma unroll
            for (int c = 0; c < 4; c++) {
                ull wvv = wv[c][j];
                acc2[0][c] = fma2(h0, wvv, acc2[0][c]);
                acc2[1][c] = fma2(h1, wvv, acc2[1][c]);
                acc2[2][c] = fma2(h2, wvv, acc2[2][c]);
                acc2[3][c] = fma2(h3, wvv, acc2[3][c]);
            }
        }
        #pragma unroll
        for (int i = 0; i < 4; i++)
            #pragma unroll
            for (int c = 0; c < 4; c++) {
                float lo, hi; unpack2(acc2[i][c], lo, hi);
                out[i][c] = lo + hi;
            }
        #pragma unroll
        for (int off = 16; off >= 1; off >>= 1)
            #pragma unroll
            for (int i = 0; i < 4; i++)
                #pragma unroll
                for (int c = 0; c < 4; c++)
                    out[i][c] += __shfl_xor_sync(0xffffffffu, out[i][c], off);
    };

    // ---- prestep: A'_{-1} = (out0 - h_init) @ Wa ----
    {
        float4 o4 = *(const float4*)&out0[b0 * H_ + tid * 4];
        float4 hi4 = *(const float4*)&h_init[b0 * H_ + tid * 4];
        *(float4*)&h_s[tid * 4] =
            make_float4(o4.x - hi4.x, o4.y - hi4.y, o4.z - hi4.z, o4.w - hi4.w);
    }
    __syncthreads();
    {
        float a0[4][4];
        do_gemm(wr2a, a0);
        if (lane < 4) {
            #pragma unroll
            for (int c = 0; c < 4; c++) A_r[c] = a0[lane][c];
        }
    }
    __syncthreads();   // h_s reuse guard before t=0 stage

    // ---- main sequential loop ----
    for (int t = 0; t < T_; t++) {
        // prefetch this step's xz early (lanes 0..3 of every warp)
        float xzv[4];
        if (lane < 4) {
            #pragma unroll
            for (int c = 0; c < 4; c++)
                xzv[c] = __ldcg(&g_xz[(size_t)(t * NZ_ + u + 256 * c) * B_ + bme]);
        }

        // wait: all 256 warps of this group finished step t-1
        if (t > 0 && tid == 0) {
            const unsigned* ctr = &g_arr[(g * T_ + (t - 1)) * 32];
            unsigned v;
            do {
                asm volatile("ld.acquire.gpu.global.u32 %0, [%1];"
                             : "=r"(v) : "l"(ctr) : "memory");
            } while (v < ARRV);
        }
        __syncthreads();   // (A) release + h_s WAR guard (also covers shadow reads)

        // stage h_{t-1} for the group's 4 batches: one float4 per thread
        {
            const float* hsrc = (t == 0) ? (h_init + b0 * H_)
                                         : (&g_h[(t - 1) & 1][b0 * H_]);
            float4 v = __ldcg((const float4*)(hsrc + tid * 4));
            *(float4*)&h_s[tid * 4] = v;
        }
        __syncthreads();   // (B)

        // critical path: ONE combined-matrix gemm
        float dWc[4][4];
        do_gemm(wr2c, dWc);

        if (lane < 4) {
            float z[4];
            #pragma unroll
            for (int c = 0; c < 4; c++)
                z[c] = xzv[c] + A_r[c] + dWc[lane][c] + bias_r[c];
            float si = fsigmoid(z[0]);
            float sf = fsigmoid(z[1]);
            float tg = ftanh_(z[2]);
            float so = fsigmoid(z[3]);
            float cn = sf * c_r + si * tg;
            float hn = so * ftanh_(cn);
            c_r = cn;
            if (t < T_ - 1) {
                __stcg(&g_h[t & 1][bme * H_ + u], hn);   // publish
                att_r += hn;                 // attens[-1] sums t<=T-2
            }
            if (t == T_ - 2) {
                dout[3 * 4096 + bme * H_ + u] = hn;      // h_prevs[-1]
                dout[4 * 4096 + bme * H_ + u] = cn;      // c_prevs[-1]
            }
            if (t == T_ - 1) {
                dout[0 * 4096 + bme * H_ + u] = hn;      // out_f (B,1,H)
                dout[1 * 4096 + bme * H_ + u] = hn;      // h_f   (1,B,H)
                dout[2 * 4096 + bme * H_ + u] = cn;      // c_f   (1,B,H)
            }
        }
        __syncwarp();                        // order this warp's h stores
        if (t < T_ - 1 && lane == 0) {
            // per-warp release-arrive (carries the warp's h stores)
            asm volatile("red.release.gpu.global.add.u32 [%0], %1;"
                         :: "l"(&g_arr[(g * T_ + t) * 32]), "r"(1u) : "memory");
        }

        // SHADOW (off critical path, hidden under next wait):
        // A'_t = A'_{t-1} + h_{t-1}@Wa.  Reads h_s; safe until next stage,
        // which every warp only reaches after its own shadow (sync A).
        if (t < T_ - 1) {
            float dWa[4][4];
            do_gemm(wr2a, dWa);
            if (lane < 4) {
                #pragma unroll
                for (int c = 0; c < 4; c++) A_r[c] += dWa[lane][c];
            }
        }
    }

    if (lane < 4)
        dout[5 * 4096 + bme * H_ + u] = att_r;           // attens[-1]
}

// ---------------------------------------------------------------------------
// inputs (metadata order): x, hidden_state, cell_state, out, Wih, Whh,
// b_ih, b_hh, W1, b1, W2, b2, W3, b3, bsize, time_step
// W1..b3 are dead (softmax over singleton axis makes weights == 1).
// ---------------------------------------------------------------------------
extern "C" void kernel_launch(void* const* d_in, const int* in_sizes, int n_in,
                              void* d_out, int out_size)
{
    const float* x       = (const float*)d_in[0];
    const float* h_init  = (const float*)d_in[1];
    const float* c_init  = (const float*)d_in[2];
    const float* out0    = (const float*)d_in[3];
    const float* Wih     = (const float*)d_in[4];
    const float* Whh     = (const float*)d_in[5];
    const float* b_ih    = (const float*)d_in[6];
    const float* b_hh    = (const float*)d_in[7];
    float* dout = (float*)d_out;

    dim3 g1(8, T_);
    xz_kernel<<<g1, 128>>>(x, Wih);
    rec_kernel<<<NBLK, 256>>>(h_init, c_init, out0, Wih, Whh, b_ih, b_hh, dout);
}

// round 14
// speedup vs baseline: 1.0529x; 1.0529x over previous
#include <cuda_runtime.h>
#include <math.h>

#define B_   16
#define T_   128
#define I_   256
#define H_   256
#define NZ_  1024          // 4*H
#define NBLK 128           // rec blocks: 4 groups x 32
#define GRPB 32            // rec arrivals per (group,step)
#define XBLK 512           // xz blocks: 8 n-blocks x 64 t-pairs
#define XARR 1024          // xz arrivals per t: 8 n-blocks x 128 threads

typedef unsigned long long ull;

// Scratch (static device globals: no allocation)
__device__ float    g_xz[T_ * NZ_ * B_];   // [t][n][b]  8 MB
__device__ float    g_h[2][B_ * H_];       // ping-pong hidden state [b][u]
__device__ unsigned g_grp[4 * T_ * 8];     // per-(group,step) counters, 32B apart
__device__ unsigned g_xzc[T_ * 8];         // per-t xz-ready counters, 32B apart

// fast transcendentals: ex2.approx + rcp.approx (~1e-6 rel err each)
__device__ __forceinline__ float fsigmoid(float x) {
    float e; asm("ex2.approx.ftz.f32 %0, %1;" : "=f"(e) : "f"(-1.4426950408889634f * x));
    float r; asm("rcp.approx.ftz.f32 %0, %1;" : "=f"(r) : "f"(1.0f + e));
    return r;
}
__device__ __forceinline__ float ftanh_(float x) {
    x = fminf(fmaxf(x, -30.0f), 30.0f);
    float e; asm("ex2.approx.ftz.f32 %0, %1;" : "=f"(e) : "f"(2.8853900817779268f * x));
    float r; asm("rcp.approx.ftz.f32 %0, %1;" : "=f"(r) : "f"(e + 1.0f));
    return (e - 1.0f) * r;
}

// packed f32x2 helpers (sm_100+)
__device__ __forceinline__ ull pack2(float lo, float hi) {
    ull r; asm("mov.b64 %0, {%1,%2};" : "=l"(r) : "f"(lo), "f"(hi)); return r;
}
__device__ __forceinline__ void unpack2(ull v, float& lo, float& hi) {
    asm("mov.b64 {%0,%1}, %2;" : "=f"(lo), "=f"(hi) : "l"(v));
}
__device__ __forceinline__ ull fma2(ull a, ull b, ull c) {
    ull d; asm("fma.rn.f32x2 %0, %1, %2, %3;" : "=l"(d) : "l"(a), "l"(b), "l"(c));
    return d;
}
__device__ __forceinline__ unsigned acq_load(const unsigned* p) {
    unsigned v;
    asm volatile("ld.acquire.gpu.global.u32 %0, [%1];" : "=r"(v) : "l"(p) : "memory");
    return v;
}
__device__ __forceinline__ void rel_red(unsigned* p) {
    asm volatile("red.release.gpu.global.add.u32 [%0], %1;" :: "l"(p), "r"(1u) : "memory");
}

// ---------------------------------------------------------------------------
// reset kernel: zero all counters (graph-replay safe, runs before fused)
// ---------------------------------------------------------------------------
__global__ void __launch_bounds__(256)
reset_kernel()
{
    for (int i = threadIdx.x; i < 4 * T_ * 8; i += 256) g_grp[i] = 0u;
    for (int i = threadIdx.x; i < T_ * 8; i += 256)     g_xzc[i] = 0u;
}

// ---------------------------------------------------------------------------
// xz producer part: block handles 2 timesteps (halves share the W panel).
// xbid in [0, XBLK): n0 = (xbid&7)*128, t = (xbid>>3)*2 + half.
// Low t -> low bid -> scheduled first (rec consumes t in order).
// ---------------------------------------------------------------------------
__device__ void xz_part(const float* __restrict__ x,
                        const float* __restrict__ Wih, int xbid)
{
    __shared__ float x_s[2][I_ * B_];   // [half][k][b], 32 KB
    __shared__ float w_s[16 * 128];     // shared 16-row k-panel, 8 KB

    const int tid  = threadIdx.x;
    const int half = tid >> 7;          // 0/1 -> t0/t1
    const int htid = tid & 127;
    const int n0   = (xbid & 7) * 128;
    const int t    = (xbid >> 3) * 2 + half;

    // stage x[:, t, :] transposed -> x_s[half][k][b]
    for (int idx = htid; idx < B_ * I_; idx += 128) {
        int b = idx >> 8;
        int k = idx & 255;
        x_s[half][k * B_ + b] = x[(b * T_ + t) * I_ + k];
    }

    const int bq = htid >> 5;       // 0..3  -> b tile of 4
    const int ng = htid & 31;       // 0..31 -> n tile of 4
    const int b0 = bq * 4;
    const int nn = ng * 4;

    float acc[4][4];
    #pragma unroll
    for (int i = 0; i < 4; i++)
        #pragma unroll
        for (int j = 0; j < 4; j++) acc[i][j] = 0.f;

    for (int kb = 0; kb < 16; kb++) {
        __syncthreads();   // protects x_s fill (1st iter) and w_s reuse
        for (int q = tid; q < 512; q += 256) {      // all 256 threads stage w_s
            int r  = q >> 5;
            int c4 = q & 31;
            ((float4*)w_s)[q] =
                ((const float4*)(Wih + (size_t)(kb * 16 + r) * NZ_ + n0))[c4];
        }
        __syncthreads();
        #pragma unroll
        for (int kk = 0; kk < 16; kk++) {
            float4 xv = *(const float4*)&x_s[half][(kb * 16 + kk) * B_ + b0];
            float4 wv = *(const float4*)&w_s[kk * 128 + nn];
            float xr[4] = {xv.x, xv.y, xv.z, xv.w};
            float wr_[4] = {wv.x, wv.y, wv.z, wv.w};
            #pragma unroll
            for (int i = 0; i < 4; i++)
                #pragma unroll
                for (int j = 0; j < 4; j++)
                    acc[i][j] += xr[i] * wr_[j];
        }
    }

    #pragma unroll
    for (int j = 0; j < 4; j++) {
        float4 o = make_float4(acc[0][j], acc[1][j], acc[2][j], acc[3][j]);
        *(float4*)&g_xz[(size_t)(t * NZ_ + n0 + nn + j) * B_ + b0] = o;
    }
    // per-thread release: orders this thread's stores; 1024 arrivals per t
    rel_red(&g_xzc[t * 8]);
}

// ---------------------------------------------------------------------------
// rec part: EXACT round-10 structure (best: 329 us), 4 groups x 32 blocks,
// warp = unit, d_s + warp0 epilogue, tid0 red per block (target GRPB=32).
// Only delta: tid0 additionally polls the xz-ready counter for step t,
// issued back-to-back with the group poll (no extra serial trip).
// ---------------------------------------------------------------------------
__device__ void rec_part(const float* __restrict__ h_init,
                         const float* __restrict__ c_init,
                         const float* __restrict__ out0,
                         const float* __restrict__ Wih,
                         const float* __restrict__ Whh,
                         const float* __restrict__ b_ih,
                         const float* __restrict__ b_hh,
                         float* __restrict__ dout)
{
    __shared__ float h_s[4 * H_];           // 4 KB: the group's 4 batches
    __shared__ float d_s[8][2][4][4];       // [unit][mat][gate][batch]
    __shared__ float A_s[8][4][4];          // running atten@Wa
    __shared__ float c_s[8][4];
    __shared__ float att_s[8][4];
    __shared__ float bias_s[8][4];

    const int tid  = threadIdx.x;
    const int bid  = blockIdx.x;
    const int g    = bid >> 5;     // group 0..3 -> batches 4g..4g+3
    const int r    = bid & 31;     // unit block -> units 8r..8r+7
    const int u0   = r * 8;
    const int b0   = g * 4;
    const int w    = tid >> 5;     // warp = local unit lu (0..7)
    const int lane = tid & 31;
    const int cs   = lane >> 4;    // 0 -> Whh, 1 -> Wa (Wih rows 256..511)
    const int kc   = lane & 15;    // k-pair base = 32*j + 2*kc

    // packed weight slice in registers: wr2[c][j] = {W[k0][n], W[k0+1][n]}
    ull wr2[4][8];
    #pragma unroll
    for (int c = 0; c < 4; c++) {
        const int n = u0 + w + 256 * c;
        #pragma unroll
        for (int j = 0; j < 8; j++) {
            const int k0 = 32 * j + 2 * kc;
            float w0 = cs ? Wih[(size_t)(256 + k0) * NZ_ + n]
                          : Whh[(size_t)k0 * NZ_ + n];
            float w1 = cs ? Wih[(size_t)(256 + k0 + 1) * NZ_ + n]
                          : Whh[(size_t)(k0 + 1) * NZ_ + n];
            wr2[c][j] = pack2(w0, w1);
        }
    }

    if (tid < 32) {
        int lu = tid >> 2, c = tid & 3;          // bias per (unit, gate)
        bias_s[lu][c] = b_ih[u0 + lu + 256 * c] + b_hh[u0 + lu + 256 * c];
    }
    if (tid < 32) {
        int lu = tid >> 2, bl = tid & 3;
        int b = b0 + bl, u = u0 + lu;
        c_s[lu][bl]   = c_init[b * H_ + u];
        att_s[lu][bl] = out0[b * H_ + u];        // atten includes buf[0] = out0
    }

    auto do_gemm = [&]() {
        ull acc2[4][4];                          // [batch][gate]
        #pragma unroll
        for (int i = 0; i < 4; i++)
            #pragma unroll
            for (int c = 0; c < 4; c++) acc2[i][c] = pack2(0.f, 0.f);
        #pragma unroll
        for (int j = 0; j < 8; j++) {
            const int k0 = 32 * j + 2 * kc;
            ull h0 = *(const ull*)&h_s[0 * H_ + k0];
            ull h1 = *(const ull*)&h_s[1 * H_ + k0];
            ull h2 = *(const ull*)&h_s[2 * H_ + k0];
            ull h3 = *(const ull*)&h_s[3 * H_ + k0];
            #pragma unroll
            for (int c = 0; c < 4; c++) {
                ull wv = wr2[c][j];
                acc2[0][c] = fma2(h0, wv, acc2[0][c]);
                acc2[1][c] = fma2(h1, wv, acc2[1][c]);
                acc2[2][c] = fma2(h2, wv, acc2[2][c]);
                acc2[3][c] = fma2(h3, wv, acc2[3][c]);
            }
        }
        float acc[4][4];
        #pragma unroll
        for (int i = 0; i < 4; i++)
            #pragma unroll
            for (int c = 0; c < 4; c++) {
                float lo, hi; unpack2(acc2[i][c], lo, hi);
                acc[i][c] = lo + hi;
            }
        // butterfly-allreduce over the 16 kc lanes (stays within cs halves)
        #pragma unroll
        for (int off = 8; off >= 1; off >>= 1)
            #pragma unroll
            for (int i = 0; i < 4; i++)
                #pragma unroll
                for (int c = 0; c < 4; c++)
                    acc[i][c] += __shfl_xor_sync(0xffffffffu, acc[i][c], off);
        if (kc == 0) {
            #pragma unroll
            for (int i = 0; i < 4; i++)
                #pragma unroll
                for (int c = 0; c < 4; c++)
                    d_s[w][cs][c][i] = acc[i][c];
        }
    };

    // ---- prestep: A_0 = out0 @ Wa  (out0 excluded from h recurrence) ----
    *(float4*)&h_s[tid * 4] = *(const float4*)&out0[b0 * H_ + tid * 4];
    __syncthreads();
    do_gemm();
    __syncthreads();
    if (tid < 32) {
        int lu = tid >> 2, bl = tid & 3;
        #pragma unroll
        for (int c = 0; c < 4; c++) A_s[lu][c][bl] = d_s[lu][1][c][bl];
    }

    // ---- main sequential loop (round-10 skeleton) ----
    for (int t = 0; t < T_; t++) {
        // wait: xz[t] produced AND (t>0) all 32 group blocks finished t-1.
        // Both acquire loads issued back-to-back -> overlapped round trips.
        if (tid == 0) {
            const unsigned* xc = &g_xzc[t * 8];
            const unsigned* gc = &g_grp[(g * T_ + (t - 1)) * 8];
            unsigned vx = acq_load(xc);
            unsigned vg = (t > 0) ? acq_load(gc) : GRPB;
            while (vx < XARR) vx = acq_load(xc);
            while (vg < GRPB) vg = acq_load(gc);
        }
        __syncthreads();   // (A) release + h_s/d_s reuse guard

        // prefetch this step's xz (ordered after acquire via the bar);
        // latency hides under stage + gemm before the epilogue consumes it
        float xzv[4];
        const int lu = (tid & 31) >> 2;
        const int bl = tid & 3;
        if (tid < 32) {
            #pragma unroll
            for (int c = 0; c < 4; c++)
                xzv[c] = __ldcg(&g_xz[(size_t)(t * NZ_ + (u0 + lu) + 256 * c) * B_ + (b0 + bl)]);
        }

        // stage h_{t-1} for the group's 4 batches: one float4 per thread
        {
            const float* hsrc = (t == 0) ? (h_init + b0 * H_)
                                         : (&g_h[(t - 1) & 1][b0 * H_]);
            float4 v = __ldcg((const float4*)(hsrc + tid * 4));
            *(float4*)&h_s[tid * 4] = v;
        }
        __syncthreads();   // (B)

        do_gemm();
        __syncthreads();   // (C)

        if (tid < 32) {
            const int u = u0 + lu;
            const int b = b0 + bl;
            float z[4];
            #pragma unroll
            for (int c = 0; c < 4; c++) {
                float Av = A_s[lu][c][bl];
                if (t > 0) Av += d_s[lu][1][c][bl];  // A_t = A_{t-1} + h_{t-1}@Wa
                A_s[lu][c][bl] = Av;
                z[c] = xzv[c] + Av + d_s[lu][0][c][bl] + bias_s[lu][c];
            }
            float si = fsigmoid(z[0]);
            float sf = fsigmoid(z[1]);
            float tg = ftanh_(z[2]);
            float so = fsigmoid(z[3]);
            float cn = sf * c_s[lu][bl] + si * tg;
            float hn = so * ftanh_(cn);
            // publish + release FIRST (critical path), bookkeeping after
            if (t < T_ - 1) {
                __stcg(&g_h[t & 1][b * H_ + u], hn);
                __syncwarp();
                if (tid == 0) rel_red(&g_grp[(g * T_ + t) * 8]);
            }
            c_s[lu][bl] = cn;
            if (t < T_ - 1) att_s[lu][bl] += hn;     // attens[-1] sums t<=T-2
            if (t == T_ - 2) {
                dout[3 * 4096 + b * H_ + u] = hn;    // h_prevs[-1]
                dout[4 * 4096 + b * H_ + u] = cn;    // c_prevs[-1]
            }
            if (t == T_ - 1) {
                dout[0 * 4096 + b * H_ + u] = hn;    // out_f (B,1,H)
                dout[1 * 4096 + b * H_ + u] = hn;    // h_f   (1,B,H)
                dout[2 * 4096 + b * H_ + u] = cn;    // c_f   (1,B,H)
            }
        }
    }

    if (tid < 32) {
        int lu2 = tid >> 2, bl2 = tid & 3;
        dout[5 * 4096 + (b0 + bl2) * H_ + (u0 + lu2)] = att_s[lu2][bl2];
    }
}

// ---------------------------------------------------------------------------
// fused kernel: blocks [0,128) = recurrence, [128,640) = xz producers.
// ---------------------------------------------------------------------------
__global__ void __launch_bounds__(256)
fused_kernel(const float* __restrict__ h_init, const float* __restrict__ c_init,
             const float* __restrict__ out0,  const float* __restrict__ x,
             const float* __restrict__ Wih,   const float* __restrict__ Whh,
             const float* __restrict__ b_ih,  const float* __restrict__ b_hh,
             float* __restrict__ dout)
{
    if (blockIdx.x >= NBLK) {
        xz_part(x, Wih, blockIdx.x - NBLK);
        return;
    }
    rec_part(h_init, c_init, out0, Wih, Whh, b_ih, b_hh, dout);
}

// ---------------------------------------------------------------------------
// inputs (metadata order): x, hidden_state, cell_state, out, Wih, Whh,
// b_ih, b_hh, W1, b1, W2, b2, W3, b3, bsize, time_step
// W1..b3 are dead (softmax over singleton axis makes weights == 1).
// ---------------------------------------------------------------------------
extern "C" void kernel_launch(void* const* d_in, const int* in_sizes, int n_in,
                              void* d_out, int out_size)
{
    const float* x       = (const float*)d_in[0];
    const float* h_init  = (const float*)d_in[1];
    const float* c_init  = (const float*)d_in[2];
    const float* out0    = (const float*)d_in[3];
    const float* Wih     = (const float*)d_in[4];
    const float* Whh     = (const float*)d_in[5];
    const float* b_ih    = (const float*)d_in[6];
    const float* b_hh    = (const float*)d_in[7];
    float* dout = (float*)d_out;

    reset_kernel<<<1, 256>>>();
    fused_kernel<<<NBLK + XBLK, 256>>>(h_init, c_init, out0, x,
                                       Wih, Whh, b_ih, b_hh, dout);
}